// round 2
// baseline (speedup 1.0000x reference)
#include <cuda_runtime.h>

#define NN    20000
#define KIN   32
#define KOUT  32
#define BR    48          // rows per block
#define BJ    32          // j tile
#define BRP   52          // padded As row (bank spread + alignment)
#define GRID1 444         // 3 * 148 -> exactly 3 CTAs per SM, balanced
#define SBLK  148         // stat-reduction blocks
#define NCHUNK 2500       // 20000 / 8 row-chunks for kernel2

// ---- scratch (device globals: no allocations allowed) ----
__device__ __align__(16) float g_H  [NN * KIN];
__device__ __align__(16) float g_H2 [NN * KOUT];
__device__ __align__(16) float g_part[SBLK * KOUT];
__device__ __align__(16) float g_psq [SBLK * KOUT];
__device__ __align__(16) float g_scale[KOUT];
__device__ __align__(16) float g_shift[KOUT];

__device__ __forceinline__ unsigned long long splat2(float a) {
    unsigned long long r;
    asm("mov.b64 %0, {%1, %1};" : "=l"(r) : "f"(a));
    return r;
}
__device__ __forceinline__ unsigned long long fma2(unsigned long long a,
                                                   unsigned long long b,
                                                   unsigned long long c) {
    unsigned long long d;
    asm("fma.rn.f32x2 %0, %1, %2, %3;" : "=l"(d) : "l"(a), "l"(b), "l"(c));
    return d;
}

// ================= Kernel 1: H = A @ X  (the whole cost) =================
// 128 threads: cg = tid&7 (8 col-groups x 4 cols), rt = tid>>3 (16 row-threads x 3 rows)
__global__ __launch_bounds__(128, 3)
void k_gemm1(const float* __restrict__ A, const float* __restrict__ X) {
    __shared__ float As[BJ][BRP];   // transposed A tile: As[j][row]
    __shared__ float Xs[BJ][KIN];

    const int tid = threadIdx.x;
    const int cg  = tid & 7;
    const int rt  = tid >> 3;
    const int i0  = blockIdx.x * BR;

    unsigned long long acc[3][2];
#pragma unroll
    for (int u = 0; u < 3; u++) { acc[u][0] = 0ULL; acc[u][1] = 0ULL; }

    for (int jt = 0; jt < NN; jt += BJ) {
        // load A tile (48 x 32) transposed into As; guard padded rows
#pragma unroll
        for (int s = 0; s < 3; s++) {
            int f  = tid + 128 * s;          // 0..383 float4 slots
            int r  = f >> 3;                 // 0..47
            int c4 = f & 7;                  // 0..7
            int gi = i0 + r;
            float4 v = make_float4(0.f, 0.f, 0.f, 0.f);
            if (gi < NN) v = *(const float4*)(A + gi * NN + jt + c4 * 4);
            As[c4 * 4 + 0][r] = v.x;
            As[c4 * 4 + 1][r] = v.y;
            As[c4 * 4 + 2][r] = v.z;
            As[c4 * 4 + 3][r] = v.w;
        }
        // load X tile (32 x 32), no transpose
#pragma unroll
        for (int s = 0; s < 2; s++) {
            int f  = tid + 128 * s;          // 0..255
            int r  = f >> 3;
            int c4 = f & 7;
            *(float4*)(&Xs[r][c4 * 4]) = *(const float4*)(X + (jt + r) * KIN + c4 * 4);
        }
        __syncthreads();

#pragma unroll
        for (int jj = 0; jj < BJ; jj++) {
            ulonglong2 xv = *(const ulonglong2*)(&Xs[jj][4 * cg]);   // 4 cols = 2 f32x2
            float a0 = As[jj][3 * rt + 0];
            float a1 = As[jj][3 * rt + 1];
            float a2 = As[jj][3 * rt + 2];
            unsigned long long s0 = splat2(a0);
            unsigned long long s1 = splat2(a1);
            unsigned long long s2 = splat2(a2);
            acc[0][0] = fma2(s0, xv.x, acc[0][0]);
            acc[0][1] = fma2(s0, xv.y, acc[0][1]);
            acc[1][0] = fma2(s1, xv.x, acc[1][0]);
            acc[1][1] = fma2(s1, xv.y, acc[1][1]);
            acc[2][0] = fma2(s2, xv.x, acc[2][0]);
            acc[2][1] = fma2(s2, xv.y, acc[2][1]);
        }
        __syncthreads();
    }

#pragma unroll
    for (int u = 0; u < 3; u++) {
        int i = i0 + 3 * rt + u;
        if (i < NN) {
            ulonglong2 v;
            v.x = acc[u][0];
            v.y = acc[u][1];
            *(ulonglong2*)(g_H + i * KIN + 4 * cg) = v;   // 16B aligned: 16*(8i+cg)
        }
    }
}

// ============ Kernel 2: H2 = H @ W  + deterministic BN partials ============
// block (32,8): tx = col, ty = row-in-chunk. Fixed-order sums -> deterministic.
__global__ void k_gemm2(const float* __restrict__ W) {
    __shared__ float Ws[KIN][KOUT];
    __shared__ float Hs[8][KIN];
    __shared__ float red[8][KOUT];

    const int tx  = threadIdx.x;
    const int ty  = threadIdx.y;
    const int tid = ty * 32 + tx;

#pragma unroll
    for (int s = 0; s < 4; s++) {
        int f = tid + 256 * s;
        Ws[f >> 5][f & 31] = W[f];
    }
    __syncthreads();

    float sum = 0.f, sq = 0.f;
    for (int c = blockIdx.x; c < NCHUNK; c += SBLK) {
        int i = c * 8 + ty;
        Hs[ty][tx] = g_H[i * KIN + tx];
        __syncthreads();
        float h2 = 0.f;
#pragma unroll
        for (int k = 0; k < KIN; k++) h2 += Hs[ty][k] * Ws[k][tx];
        g_H2[i * KOUT + tx] = h2;
        sum += h2;
        sq  += h2 * h2;
        __syncthreads();
    }

    red[ty][tx] = sum;
    __syncthreads();
    if (ty == 0) {
        float s = 0.f;
#pragma unroll
        for (int y = 0; y < 8; y++) s += red[y][tx];
        g_part[blockIdx.x * KOUT + tx] = s;
    }
    __syncthreads();
    red[ty][tx] = sq;
    __syncthreads();
    if (ty == 0) {
        float s = 0.f;
#pragma unroll
        for (int y = 0; y < 8; y++) s += red[y][tx];
        g_psq[blockIdx.x * KOUT + tx] = s;
    }
}

// ============ Kernel 3: finalize BN stats (double precision) ============
__global__ void k_stats(const float* __restrict__ gamma,
                        const float* __restrict__ beta,
                        const float* __restrict__ bias) {
    int c = threadIdx.x;   // 0..31
    double s = 0.0, q = 0.0;
    for (int b = 0; b < SBLK; b++) {
        s += (double)g_part[b * KOUT + c];
        q += (double)g_psq [b * KOUT + c];
    }
    double mean = s / (double)NN;
    double var  = q / (double)NN - mean * mean;
    double inv  = 1.0 / sqrt(var + 1e-5);
    double gsc  = (double)gamma[c] * inv;
    g_scale[c] = (float)gsc;
    g_shift[c] = (float)((double)beta[c] + (double)bias[c] - mean * gsc);
}

// ============ Kernel 4: out = relu(H2 * scale + shift) ============
__global__ void k_apply(float* __restrict__ out) {
    int idx4 = blockIdx.x * blockDim.x + threadIdx.x;   // 0..159999
    float4 h  = *(const float4*)(g_H2 + idx4 * 4);
    int cb    = (idx4 * 4) & 31;
    float4 sc = *(const float4*)(g_scale + cb);
    float4 sh = *(const float4*)(g_shift + cb);
    float4 o;
    o.x = fmaxf(h.x * sc.x + sh.x, 0.f);
    o.y = fmaxf(h.y * sc.y + sh.y, 0.f);
    o.z = fmaxf(h.z * sc.z + sh.z, 0.f);
    o.w = fmaxf(h.w * sc.w + sh.w, 0.f);
    *(float4*)(out + idx4 * 4) = o;
}

// ====================== launch ======================
extern "C" void kernel_launch(void* const* d_in, const int* in_sizes, int n_in,
                              void* d_out, int out_size) {
    const float* A     = (const float*)d_in[0];
    const float* X     = (const float*)d_in[1];
    const float* W     = (const float*)d_in[2];
    const float* gamma = (const float*)d_in[3];
    const float* beta  = (const float*)d_in[4];
    const float* bias  = (const float*)d_in[5];
    float* out = (float*)d_out;

    k_gemm1<<<GRID1, 128>>>(A, X);
    k_gemm2<<<SBLK, dim3(32, 8)>>>(W);
    k_stats<<<1, KOUT>>>(gamma, beta, bias);
    k_apply<<<(NN * KOUT / 4) / 256, 256>>>(out);   // 625 blocks x 256
}

// round 5
// speedup vs baseline: 1.2057x; 1.2057x over previous
#include <cuda_runtime.h>
#include <cstdint>

#define NN     20000
#define KO     32
#define MTILE  128
#define KTILE  32
#define NTILES 625          // 20000/32 exact
#define GRID1  157          // ceil(20000/128)

#define APADF  36           // floats per smem row (stride 144B, conflict-free frags)
#define A_BYTES (128 * APADF * 4)          // 18432
#define X_BYTES (32  * APADF * 4)          // 4608
#define STAGEB  (A_BYTES + X_BYTES)        // 23040
#define NSTAGE  3
#define W_OFF   (STAGEB * NSTAGE)          // 69120
#define SMEM_TOTAL (W_OFF + 4096)          // 73216

// ---- scratch (no allocations allowed) ----
__device__ __align__(16) float g_H2  [NN * KO];
__device__ __align__(16) float g_part[GRID1 * KO];
__device__ __align__(16) float g_psq [GRID1 * KO];
__device__ float g_scale[KO];
__device__ float g_shift[KO];

// ================= helpers =================
__device__ __forceinline__ uint32_t smem_u32(const void* p) {
    uint32_t a;
    asm("{ .reg .u64 t; cvta.to.shared.u64 t, %1; cvt.u32.u64 %0, t; }" : "=r"(a) : "l"(p));
    return a;
}
__device__ __forceinline__ void cp16(uint32_t dst, const void* src, bool ok) {
    asm volatile("cp.async.cg.shared.global [%0], [%1], 16, %2;"
                 :: "r"(dst), "l"(src), "r"(ok ? 16u : 0u) : "memory");
}
#define CP_COMMIT() asm volatile("cp.async.commit_group;" ::: "memory")
#define CP_WAIT2()  asm volatile("cp.async.wait_group 2;" ::: "memory")
#define CP_WAIT0()  asm volatile("cp.async.wait_group 0;" ::: "memory")

// fp32 -> (tf32_hi, tf32_lo) split for 3xTF32
__device__ __forceinline__ void cvt3(float a, uint32_t& hi, uint32_t& lo) {
    asm("cvt.rna.tf32.f32 %0, %1;" : "=r"(hi) : "f"(a));
    float r = a - __uint_as_float(hi);
    asm("cvt.rna.tf32.f32 %0, %1;" : "=r"(lo) : "f"(r));
}
__device__ __forceinline__ void mma8(float& c0, float& c1, float& c2, float& c3,
                                     uint32_t a0, uint32_t a1, uint32_t a2, uint32_t a3,
                                     uint32_t b0, uint32_t b1) {
    asm volatile(
        "mma.sync.aligned.m16n8k8.row.col.f32.tf32.tf32.f32 "
        "{%0,%1,%2,%3}, {%4,%5,%6,%7}, {%8,%9}, {%0,%1,%2,%3};"
        : "+f"(c0), "+f"(c1), "+f"(c2), "+f"(c3)
        : "r"(a0), "r"(a1), "r"(a2), "r"(a3), "r"(b0), "r"(b1));
}

// ============ Kernel 1: H = A@X (3xTF32 mma.sync) + fused @W + BN partials ============
__global__ __launch_bounds__(128)
void k_gemm1(const float* __restrict__ A, const float* __restrict__ X,
             const float* __restrict__ W) {
    extern __shared__ __align__(128) char sm[];
    const uint32_t smb = smem_u32(sm);
    const int tid  = threadIdx.x;
    const int wid  = tid >> 5;
    const int lane = tid & 31;
    const int g    = lane >> 2;       // groupID 0..7
    const int tq   = lane & 3;        // thread-in-group 0..3
    const size_t m0 = (size_t)blockIdx.x * MTILE;

    // W -> smem [32][32]
    float* Ws = (float*)(sm + W_OFF);
#pragma unroll
    for (int u = 0; u < 8; u++) Ws[tid + 128 * u] = W[tid + 128 * u];

    // per-thread cp.async slots: A: 8 x (row=slot/8, c4=slot%8); X: 2 slots
    const int arow[8] = { tid >> 3, (tid + 128) >> 3, (tid + 256) >> 3, (tid + 384) >> 3,
                          (tid + 512) >> 3, (tid + 640) >> 3, (tid + 768) >> 3, (tid + 896) >> 3 };
    const int ac4 = tid & 7;          // same for all slots (tid + 128u keeps low 3 bits)

    auto load_stage = [&](int s, int t) {
        const uint32_t sb = smb + s * STAGEB;
        const int k0 = t * KTILE;
#pragma unroll
        for (int u = 0; u < 8; u++) {
            int r = arow[u];
            bool ok = (m0 + r) < NN;
            cp16(sb + (uint32_t)(r * APADF + ac4 * 4) * 4,
                 A + (m0 + r) * NN + k0 + ac4 * 4, ok);
        }
#pragma unroll
        for (int u = 0; u < 2; u++) {
            int slot = tid + 128 * u;
            int r = slot >> 3;        // 0..31
            cp16(sb + A_BYTES + (uint32_t)(r * APADF + ac4 * 4) * 4,
                 X + (size_t)(k0 + r) * KO + ac4 * 4, true);
        }
        CP_COMMIT();
    };

    load_stage(0, 0);
    load_stage(1, 1);
    load_stage(2, 2);

    float acc[2][4][4];
#pragma unroll
    for (int mt = 0; mt < 2; mt++)
#pragma unroll
        for (int nt = 0; nt < 4; nt++)
#pragma unroll
            for (int v = 0; v < 4; v++) acc[mt][nt][v] = 0.f;

    const int wr = wid * 32;

    for (int t = 0; t < NTILES; t++) {
        const int s = t % NSTAGE;
        CP_WAIT2();
        __syncthreads();
        const float* As = (const float*)(sm + s * STAGEB);
        const float* Xs = (const float*)(sm + s * STAGEB + A_BYTES);

#pragma unroll
        for (int ks = 0; ks < 4; ks++) {
            // ---- A fragments (2 m-tiles), rows {g,g+8}, cols {ks*8+tq, +4} ----
            uint32_t ahi[2][4], alo[2][4];
#pragma unroll
            for (int mt = 0; mt < 2; mt++) {
                int r0 = wr + mt * 16 + g;
                int c0 = ks * 8 + tq;
                cvt3(As[r0 * APADF + c0],           ahi[mt][0], alo[mt][0]);
                cvt3(As[(r0 + 8) * APADF + c0],     ahi[mt][1], alo[mt][1]);
                cvt3(As[r0 * APADF + c0 + 4],       ahi[mt][2], alo[mt][2]);
                cvt3(As[(r0 + 8) * APADF + c0 + 4], ahi[mt][3], alo[mt][3]);
            }
            // ---- B fragments (4 n-tiles), rows(k) {ks*8+tq, +4}, col n = nt*8+g ----
            uint32_t bhi[4][2], blo[4][2];
#pragma unroll
            for (int nt = 0; nt < 4; nt++) {
                int kr = ks * 8 + tq;
                int nc = nt * 8 + g;
                cvt3(Xs[kr * APADF + nc],       bhi[nt][0], blo[nt][0]);
                cvt3(Xs[(kr + 4) * APADF + nc], bhi[nt][1], blo[nt][1]);
            }
#pragma unroll
            for (int mt = 0; mt < 2; mt++)
#pragma unroll
                for (int nt = 0; nt < 4; nt++) {
                    mma8(acc[mt][nt][0], acc[mt][nt][1], acc[mt][nt][2], acc[mt][nt][3],
                         ahi[mt][0], ahi[mt][1], ahi[mt][2], ahi[mt][3],
                         bhi[nt][0], bhi[nt][1]);
                    mma8(acc[mt][nt][0], acc[mt][nt][1], acc[mt][nt][2], acc[mt][nt][3],
                         ahi[mt][0], ahi[mt][1], ahi[mt][2], ahi[mt][3],
                         blo[nt][0], blo[nt][1]);
                    mma8(acc[mt][nt][0], acc[mt][nt][1], acc[mt][nt][2], acc[mt][nt][3],
                         alo[mt][0], alo[mt][1], alo[mt][2], alo[mt][3],
                         bhi[nt][0], bhi[nt][1]);
                }
        }
        __syncthreads();
        if (t + NSTAGE < NTILES) load_stage(s, t + NSTAGE);
        else CP_COMMIT();   // keep group count aligned
    }
    CP_WAIT0();

    // ---- epilogue: fragments -> smem H[128][33] ----
    __syncthreads();
    float* Hs = (float*)sm;
#pragma unroll
    for (int mt = 0; mt < 2; mt++) {
        int r0 = wr + mt * 16 + g;
#pragma unroll
        for (int nt = 0; nt < 4; nt++) {
            int cc = nt * 8 + 2 * tq;
            Hs[r0 * 33 + cc]           = acc[mt][nt][0];
            Hs[r0 * 33 + cc + 1]       = acc[mt][nt][1];
            Hs[(r0 + 8) * 33 + cc]     = acc[mt][nt][2];
            Hs[(r0 + 8) * 33 + cc + 1] = acc[mt][nt][3];
        }
    }
    __syncthreads();

    // per-thread row: h2 = h @ W, write, BN partials
    float h[32];
#pragma unroll
    for (int k = 0; k < 32; k++) h[k] = Hs[tid * 33 + k];
    __syncthreads();

    float h2[32];
#pragma unroll
    for (int n = 0; n < 32; n++) {
        float s = 0.f;
#pragma unroll
        for (int k = 0; k < 32; k++) s += h[k] * Ws[k * 32 + n];
        h2[n] = s;
    }

    size_t i = m0 + tid;
    if (i < NN) {
        float4* o = (float4*)(g_H2 + i * KO);
#pragma unroll
        for (int n4 = 0; n4 < 8; n4++)
            o[n4] = make_float4(h2[n4*4], h2[n4*4+1], h2[n4*4+2], h2[n4*4+3]);
    } else {
#pragma unroll
        for (int n = 0; n < 32; n++) h2[n] = 0.f;   // padded rows contribute 0
    }

    // deterministic fixed-order per-CTA reduction
    float* red = (float*)sm;              // [128][32]
    float* rsq = (float*)(sm + 16384);    // [128][32]
#pragma unroll
    for (int n = 0; n < 32; n++) {
        red[tid * 32 + n] = h2[n];
        rsq[tid * 32 + n] = h2[n] * h2[n];
    }
    __syncthreads();
    for (int st = 64; st > 0; st >>= 1) {
        if (tid < st) {
#pragma unroll
            for (int n = 0; n < 32; n++) {
                red[tid * 32 + n] += red[(tid + st) * 32 + n];
                rsq[tid * 32 + n] += rsq[(tid + st) * 32 + n];
            }
        }
        __syncthreads();
    }
    if (tid < 32) {
        g_part[blockIdx.x * KO + tid] = red[tid];
        g_psq [blockIdx.x * KO + tid] = rsq[tid];
    }
}

// ================= Kernel 2: finalize BN stats (double) =================
__global__ void k_stats(const float* __restrict__ gamma,
                        const float* __restrict__ beta,
                        const float* __restrict__ bias) {
    int c = threadIdx.x;
    double s = 0.0, qq = 0.0;
    for (int b = 0; b < GRID1; b++) {
        s  += (double)g_part[b * KO + c];
        qq += (double)g_psq [b * KO + c];
    }
    double mean = s / (double)NN;
    double var  = qq / (double)NN - mean * mean;
    double inv  = 1.0 / sqrt(var + 1e-5);
    double gsc  = (double)gamma[c] * inv;
    g_scale[c] = (float)gsc;
    g_shift[c] = (float)((double)beta[c] + (double)bias[c] - mean * gsc);
}

// ================= Kernel 3: out = relu(H2*scale + shift) =================
__global__ void k_apply(float* __restrict__ out) {
    int idx4 = blockIdx.x * blockDim.x + threadIdx.x;
    float4 h  = *(const float4*)(g_H2 + (size_t)idx4 * 4);
    int cb    = (idx4 * 4) & 31;
    float4 sc = *(const float4*)(g_scale + cb);
    float4 sh = *(const float4*)(g_shift + cb);
    float4 o;
    o.x = fmaxf(h.x * sc.x + sh.x, 0.f);
    o.y = fmaxf(h.y * sc.y + sh.y, 0.f);
    o.z = fmaxf(h.z * sc.z + sh.z, 0.f);
    o.w = fmaxf(h.w * sc.w + sh.w, 0.f);
    *(float4*)(out + (size_t)idx4 * 4) = o;
}

// ================= launch =================
extern "C" void kernel_launch(void* const* d_in, const int* in_sizes, int n_in,
                              void* d_out, int out_size) {
    const float* A     = (const float*)d_in[0];
    const float* X     = (const float*)d_in[1];
    const float* W     = (const float*)d_in[2];
    const float* gamma = (const float*)d_in[3];
    const float* beta  = (const float*)d_in[4];
    const float* bias  = (const float*)d_in[5];
    float* out = (float*)d_out;

    cudaFuncSetAttribute(k_gemm1, cudaFuncAttributeMaxDynamicSharedMemorySize, SMEM_TOTAL);

    k_gemm1<<<GRID1, 128, SMEM_TOTAL>>>(A, X, W);
    k_stats<<<1, KO>>>(gamma, beta, bias);
    k_apply<<<(NN * KO / 4) / 256, 256>>>(out);
}

// round 6
// speedup vs baseline: 1.7014x; 1.4112x over previous
#include <cuda_runtime.h>
#include <cstdint>

#define NN     20000
#define KO     32
#define MTILE  64
#define KTILE  32
#define NTILES 625          // 20000/32 exact
#define GRID1  313          // ceil(20000/64)

#define APADF  36                     // A smem row stride (floats)
#define XPAD2  36                     // X smem row stride (uint2); 36 mod 16 == 4 -> phase-conflict-free LDS.64
#define A_BYTES (MTILE * APADF * 4)   // 9216
#define X_BYTES (KTILE * XPAD2 * 8)   // 9216
#define STAGEB  (A_BYTES + X_BYTES)   // 18432
#define NSTAGE  3
#define W_OFF   (STAGEB * NSTAGE)     // 55296
#define SMEM_TOTAL (W_OFF + 4096)     // 59392

// ---- scratch (no allocations allowed) ----
__device__ __align__(16) uint2 g_X2 [NN * KO];      // X pre-split: (tf32_hi, tf32_lo)
__device__ __align__(16) float g_H2 [NN * KO];
__device__ __align__(16) float g_part[GRID1 * KO];
__device__ __align__(16) float g_psq [GRID1 * KO];
__device__ float g_scale[KO];
__device__ float g_shift[KO];

// ================= helpers =================
__device__ __forceinline__ uint32_t smem_u32(const void* p) {
    uint32_t a;
    asm("{ .reg .u64 t; cvta.to.shared.u64 t, %1; cvt.u32.u64 %0, t; }" : "=r"(a) : "l"(p));
    return a;
}
__device__ __forceinline__ void cp16(uint32_t dst, const void* src, bool ok) {
    asm volatile("cp.async.cg.shared.global [%0], [%1], 16, %2;"
                 :: "r"(dst), "l"(src), "r"(ok ? 16u : 0u) : "memory");
}
#define CP_COMMIT() asm volatile("cp.async.commit_group;" ::: "memory")
#define CP_WAIT2()  asm volatile("cp.async.wait_group 2;" ::: "memory")
#define CP_WAIT0()  asm volatile("cp.async.wait_group 0;" ::: "memory")

__device__ __forceinline__ void cvt3(float a, uint32_t& hi, uint32_t& lo) {
    asm("cvt.rna.tf32.f32 %0, %1;" : "=r"(hi) : "f"(a));
    float r = a - __uint_as_float(hi);
    asm("cvt.rna.tf32.f32 %0, %1;" : "=r"(lo) : "f"(r));
}
__device__ __forceinline__ void mma8(float& c0, float& c1, float& c2, float& c3,
                                     uint32_t a0, uint32_t a1, uint32_t a2, uint32_t a3,
                                     uint32_t b0, uint32_t b1) {
    asm volatile(
        "mma.sync.aligned.m16n8k8.row.col.f32.tf32.tf32.f32 "
        "{%0,%1,%2,%3}, {%4,%5,%6,%7}, {%8,%9}, {%0,%1,%2,%3};"
        : "+f"(c0), "+f"(c1), "+f"(c2), "+f"(c3)
        : "r"(a0), "r"(a1), "r"(a2), "r"(a3), "r"(b0), "r"(b1));
}

// ============ Kernel 0: split X into (hi, lo) tf32 pairs ============
__global__ void k_prep(const float* __restrict__ X) {
    int i = blockIdx.x * blockDim.x + threadIdx.x;   // < 640000
    float x = X[i];
    uint32_t hi, lo;
    cvt3(x, hi, lo);
    g_X2[i] = make_uint2(hi, lo);
}

// ============ Kernel 1: H = A@X (3xTF32 mma.sync) + fused @W + BN partials ============
__global__ __launch_bounds__(128)
void k_gemm1(const float* __restrict__ A, const float* __restrict__ W) {
    extern __shared__ __align__(128) char sm[];
    const uint32_t smb = smem_u32(sm);
    const int tid  = threadIdx.x;
    const int wid  = tid >> 5;
    const int lane = tid & 31;
    const int g    = lane >> 2;       // 0..7
    const int tq   = lane & 3;        // 0..3
    const size_t m0 = (size_t)blockIdx.x * MTILE;

    // W -> smem [32][32]
    float* Ws = (float*)(sm + W_OFF);
#pragma unroll
    for (int u = 0; u < 8; u++) Ws[tid + 128 * u] = W[tid + 128 * u];

    auto load_stage = [&](int s, int t) {
        const uint32_t sb = smb + s * STAGEB;
        const int k0 = t * KTILE;
        // A: 64 rows x 32 floats = 512 x 16B
#pragma unroll
        for (int u = 0; u < 4; u++) {
            int slot = tid + 128 * u;
            int r  = slot >> 3;               // 0..63
            int c4 = slot & 7;
            bool ok = (m0 + r) < NN;
            cp16(sb + (uint32_t)(r * APADF + c4 * 4) * 4,
                 A + (m0 + r) * NN + k0 + c4 * 4, ok);
        }
        // X2: 32 rows x 32 uint2 = 512 x 16B (2 uint2 per 16B)
#pragma unroll
        for (int u = 0; u < 4; u++) {
            int slot = tid + 128 * u;
            int r  = slot >> 4;               // 0..31
            int c2 = slot & 15;               // uint2-pair index
            cp16(sb + A_BYTES + (uint32_t)(r * XPAD2 + c2 * 2) * 8,
                 g_X2 + (size_t)(k0 + r) * KO + c2 * 2, true);
        }
        CP_COMMIT();
    };

    load_stage(0, 0);
    load_stage(1, 1);
    load_stage(2, 2);

    float acc[4][4];
#pragma unroll
    for (int nt = 0; nt < 4; nt++)
#pragma unroll
        for (int v = 0; v < 4; v++) acc[nt][v] = 0.f;

    const int wr = wid * 16;

    for (int t = 0; t < NTILES; t++) {
        const int s = t % NSTAGE;
        CP_WAIT2();
        __syncthreads();
        const float* As = (const float*)(sm + s * STAGEB);
        const uint2* Xs = (const uint2*)(sm + s * STAGEB + A_BYTES);

#pragma unroll
        for (int ks = 0; ks < 4; ks++) {
            // A fragment: rows {wr+g, wr+g+8}, cols {ks*8+tq, +4}
            uint32_t ahi[4], alo[4];
            {
                int r0 = wr + g;
                int c0 = ks * 8 + tq;
                cvt3(As[r0 * APADF + c0],           ahi[0], alo[0]);
                cvt3(As[(r0 + 8) * APADF + c0],     ahi[1], alo[1]);
                cvt3(As[r0 * APADF + c0 + 4],       ahi[2], alo[2]);
                cvt3(As[(r0 + 8) * APADF + c0 + 4], ahi[3], alo[3]);
            }
#pragma unroll
            for (int nt = 0; nt < 4; nt++) {
                int kr = ks * 8 + tq;
                int nc = nt * 8 + g;
                uint2 v0 = Xs[kr * XPAD2 + nc];
                uint2 v1 = Xs[(kr + 4) * XPAD2 + nc];
                mma8(acc[nt][0], acc[nt][1], acc[nt][2], acc[nt][3],
                     ahi[0], ahi[1], ahi[2], ahi[3], v0.x, v1.x);
                mma8(acc[nt][0], acc[nt][1], acc[nt][2], acc[nt][3],
                     ahi[0], ahi[1], ahi[2], ahi[3], v0.y, v1.y);
                mma8(acc[nt][0], acc[nt][1], acc[nt][2], acc[nt][3],
                     alo[0], alo[1], alo[2], alo[3], v0.x, v1.x);
            }
        }
        __syncthreads();
        if (t + NSTAGE < NTILES) load_stage(s, t + NSTAGE);
        else CP_COMMIT();   // keep group count aligned
    }
    CP_WAIT0();

    // ---- epilogue: fragments -> smem H[64][33] ----
    __syncthreads();
    float* Hs = (float*)sm;
    {
        int r0 = wr + g;
#pragma unroll
        for (int nt = 0; nt < 4; nt++) {
            int cc = nt * 8 + 2 * tq;
            Hs[r0 * 33 + cc]           = acc[nt][0];
            Hs[r0 * 33 + cc + 1]       = acc[nt][1];
            Hs[(r0 + 8) * 33 + cc]     = acc[nt][2];
            Hs[(r0 + 8) * 33 + cc + 1] = acc[nt][3];
        }
    }
    __syncthreads();

    // threads 0..63: one H row each: h2 = h @ W, write, square
    float h2[32];
    if (tid < MTILE) {
        float h[32];
#pragma unroll
        for (int k = 0; k < 32; k++) h[k] = Hs[tid * 33 + k];
#pragma unroll
        for (int n = 0; n < 32; n++) {
            float s = 0.f;
#pragma unroll
            for (int k = 0; k < 32; k++) s += h[k] * Ws[k * 32 + n];
            h2[n] = s;
        }
        size_t i = m0 + tid;
        if (i < NN) {
            float4* o = (float4*)(g_H2 + i * KO);
#pragma unroll
            for (int n4 = 0; n4 < 8; n4++)
                o[n4] = make_float4(h2[n4*4], h2[n4*4+1], h2[n4*4+2], h2[n4*4+3]);
        } else {
#pragma unroll
            for (int n = 0; n < 32; n++) h2[n] = 0.f;
        }
    }

    // deterministic fixed-order per-CTA reduction over 64 rows
    __syncthreads();
    float* red = (float*)sm;              // [64][32]
    float* rsq = (float*)(sm + 8192);     // [64][32]
    if (tid < MTILE) {
#pragma unroll
        for (int n = 0; n < 32; n++) {
            red[tid * 32 + n] = h2[n];
            rsq[tid * 32 + n] = h2[n] * h2[n];
        }
    }
    __syncthreads();
    for (int st = 32; st > 0; st >>= 1) {
        if (tid < st) {
#pragma unroll
            for (int n = 0; n < 32; n++) {
                red[tid * 32 + n] += red[(tid + st) * 32 + n];
                rsq[tid * 32 + n] += rsq[(tid + st) * 32 + n];
            }
        }
        __syncthreads();
    }
    if (tid < 32) {
        g_part[blockIdx.x * KO + tid] = red[tid];
        g_psq [blockIdx.x * KO + tid] = rsq[tid];
    }
}

// ================= Kernel 2: finalize BN stats (double) =================
__global__ void k_stats(const float* __restrict__ gamma,
                        const float* __restrict__ beta,
                        const float* __restrict__ bias) {
    int c = threadIdx.x;
    double s = 0.0, qq = 0.0;
    for (int b = 0; b < GRID1; b++) {
        s  += (double)g_part[b * KO + c];
        qq += (double)g_psq [b * KO + c];
    }
    double mean = s / (double)NN;
    double var  = qq / (double)NN - mean * mean;
    double inv  = 1.0 / sqrt(var + 1e-5);
    double gsc  = (double)gamma[c] * inv;
    g_scale[c] = (float)gsc;
    g_shift[c] = (float)((double)beta[c] + (double)bias[c] - mean * gsc);
}

// ================= Kernel 3: out = relu(H2*scale + shift) =================
__global__ void k_apply(float* __restrict__ out) {
    int idx4 = blockIdx.x * blockDim.x + threadIdx.x;
    float4 h  = *(const float4*)(g_H2 + (size_t)idx4 * 4);
    int cb    = (idx4 * 4) & 31;
    float4 sc = *(const float4*)(g_scale + cb);
    float4 sh = *(const float4*)(g_shift + cb);
    float4 o;
    o.x = fmaxf(h.x * sc.x + sh.x, 0.f);
    o.y = fmaxf(h.y * sc.y + sh.y, 0.f);
    o.z = fmaxf(h.z * sc.z + sh.z, 0.f);
    o.w = fmaxf(h.w * sc.w + sh.w, 0.f);
    *(float4*)(out + (size_t)idx4 * 4) = o;
}

// ================= launch =================
extern "C" void kernel_launch(void* const* d_in, const int* in_sizes, int n_in,
                              void* d_out, int out_size) {
    const float* A     = (const float*)d_in[0];
    const float* X     = (const float*)d_in[1];
    const float* W     = (const float*)d_in[2];
    const float* gamma = (const float*)d_in[3];
    const float* beta  = (const float*)d_in[4];
    const float* bias  = (const float*)d_in[5];
    float* out = (float*)d_out;

    cudaFuncSetAttribute(k_gemm1, cudaFuncAttributeMaxDynamicSharedMemorySize, SMEM_TOTAL);

    k_prep<<<(NN * KO) / 256, 256>>>(X);
    k_gemm1<<<GRID1, 128, SMEM_TOTAL>>>(A, W);
    k_stats<<<1, KO>>>(gamma, beta, bias);
    k_apply<<<(NN * KO / 4) / 256, 256>>>(out);
}

// round 7
// speedup vs baseline: 1.9293x; 1.1340x over previous
#include <cuda_runtime.h>
#include <cstdint>

#define NN     20000
#define KO     32
#define MTILE  64
#define KTILE  32
#define NTILES 625          // 20000/32 exact
#define GRID1  313          // ceil(20000/64)

#define APADF  36                     // A smem row stride (floats)
#define XPADF  40                     // X smem row stride (floats): bank = 8*tq+g -> perfect
#define A_BYTES (MTILE * APADF * 4)   // 9216
#define X_BYTES (KTILE * XPADF * 4)   // 5120
#define STAGEB  (A_BYTES + X_BYTES)   // 14336
#define NSTAGE  3
#define W_OFF   (STAGEB * NSTAGE)     // 43008
#define SMEM_TOTAL (W_OFF + 4096)     // 47104

// ---- scratch (no allocations allowed) ----
__device__ __align__(16) float g_H2 [NN * KO];
__device__ __align__(16) float g_part[GRID1 * KO];
__device__ __align__(16) float g_psq [GRID1 * KO];
__device__ float g_scale[KO];
__device__ float g_shift[KO];

// ================= helpers =================
__device__ __forceinline__ uint32_t smem_u32(const void* p) {
    uint32_t a;
    asm("{ .reg .u64 t; cvta.to.shared.u64 t, %1; cvt.u32.u64 %0, t; }" : "=r"(a) : "l"(p));
    return a;
}
__device__ __forceinline__ void cp16(uint32_t dst, const void* src, bool ok) {
    asm volatile("cp.async.cg.shared.global [%0], [%1], 16, %2;"
                 :: "r"(dst), "l"(src), "r"(ok ? 16u : 0u) : "memory");
}
#define CP_COMMIT() asm volatile("cp.async.commit_group;" ::: "memory")
#define CP_WAIT2()  asm volatile("cp.async.wait_group 2;" ::: "memory")
#define CP_WAIT0()  asm volatile("cp.async.wait_group 0;" ::: "memory")

__device__ __forceinline__ void cvt3(float a, uint32_t& hi, uint32_t& lo) {
    asm("cvt.rna.tf32.f32 %0, %1;" : "=r"(hi) : "f"(a));
    float r = a - __uint_as_float(hi);
    asm("cvt.rna.tf32.f32 %0, %1;" : "=r"(lo) : "f"(r));
}
__device__ __forceinline__ void mma8(float& c0, float& c1, float& c2, float& c3,
                                     uint32_t a0, uint32_t a1, uint32_t a2, uint32_t a3,
                                     uint32_t b0, uint32_t b1) {
    asm volatile(
        "mma.sync.aligned.m16n8k8.row.col.f32.tf32.tf32.f32 "
        "{%0,%1,%2,%3}, {%4,%5,%6,%7}, {%8,%9}, {%0,%1,%2,%3};"
        : "+f"(c0), "+f"(c1), "+f"(c2), "+f"(c3)
        : "r"(a0), "r"(a1), "r"(a2), "r"(a3), "r"(b0), "r"(b1));
}

// ====== Kernel 1: H = A@X (3xTF32, K-split warps) + fused @W + BN partials ======
__global__ __launch_bounds__(128)
void k_gemm1(const float* __restrict__ A, const float* __restrict__ X,
             const float* __restrict__ W) {
    extern __shared__ __align__(128) char sm[];
    const uint32_t smb = smem_u32(sm);
    const int tid  = threadIdx.x;
    const int wid  = tid >> 5;        // warp owns k-cols [8*wid, 8*wid+8)
    const int lane = tid & 31;
    const int g    = lane >> 2;       // 0..7
    const int tq   = lane & 3;        // 0..3
    const size_t m0 = (size_t)blockIdx.x * MTILE;

    // W -> smem [32][32]
    float* Ws = (float*)(sm + W_OFF);
#pragma unroll
    for (int u = 0; u < 8; u++) Ws[tid + 128 * u] = W[tid + 128 * u];

    auto load_stage = [&](int s, int t) {
        const uint32_t sb = smb + s * STAGEB;
        const int k0 = t * KTILE;
        // A: 64 rows x 32 floats = 512 x 16B slots
#pragma unroll
        for (int u = 0; u < 4; u++) {
            int slot = tid + 128 * u;
            int r  = slot >> 3;               // 0..63
            int c4 = slot & 7;
            bool ok = (m0 + r) < NN;
            cp16(sb + (uint32_t)(r * APADF + c4 * 4) * 4,
                 A + (m0 + r) * NN + k0 + c4 * 4, ok);
        }
        // X: 32 rows x 32 floats = 256 x 16B slots
#pragma unroll
        for (int u = 0; u < 2; u++) {
            int slot = tid + 128 * u;
            int r  = slot >> 3;               // 0..31
            int c4 = slot & 7;
            cp16(sb + A_BYTES + (uint32_t)(r * XPADF + c4 * 4) * 4,
                 X + (size_t)(k0 + r) * KO + c4 * 4, true);
        }
        CP_COMMIT();
    };

    load_stage(0, 0);
    load_stage(1, 1);
    load_stage(2, 2);

    // acc[mt][nt][v]: full 64 rows x 32 cols, partial over this warp's k-cols
    float acc[4][4][4];
#pragma unroll
    for (int mt = 0; mt < 4; mt++)
#pragma unroll
        for (int nt = 0; nt < 4; nt++)
#pragma unroll
            for (int v = 0; v < 4; v++) acc[mt][nt][v] = 0.f;

    const int ksc = wid * 8;          // this warp's k-column base

    for (int t = 0; t < NTILES; t++) {
        const int s = t % NSTAGE;
        CP_WAIT2();
        __syncthreads();
        const float* As = (const float*)(sm + s * STAGEB);
        const float* Xs = (const float*)(sm + s * STAGEB + A_BYTES);

        // X fragments for this warp's k-slice: 8 floats -> (hi,lo)
        uint32_t bhi[4][2], blo[4][2];
        const int kr = ksc + tq;
#pragma unroll
        for (int nt = 0; nt < 4; nt++) {
            int nc = nt * 8 + g;
            cvt3(Xs[kr * XPADF + nc],       bhi[nt][0], blo[nt][0]);
            cvt3(Xs[(kr + 4) * XPADF + nc], bhi[nt][1], blo[nt][1]);
        }
        // A fragments: 4 m-tiles x 4 values
        uint32_t ahi[4][4], alo[4][4];
        const int c0 = ksc + tq;
#pragma unroll
        for (int mt = 0; mt < 4; mt++) {
            int r0 = mt * 16 + g;
            cvt3(As[r0 * APADF + c0],           ahi[mt][0], alo[mt][0]);
            cvt3(As[(r0 + 8) * APADF + c0],     ahi[mt][1], alo[mt][1]);
            cvt3(As[r0 * APADF + c0 + 4],       ahi[mt][2], alo[mt][2]);
            cvt3(As[(r0 + 8) * APADF + c0 + 4], ahi[mt][3], alo[mt][3]);
        }
#pragma unroll
        for (int mt = 0; mt < 4; mt++)
#pragma unroll
            for (int nt = 0; nt < 4; nt++) {
                mma8(acc[mt][nt][0], acc[mt][nt][1], acc[mt][nt][2], acc[mt][nt][3],
                     ahi[mt][0], ahi[mt][1], ahi[mt][2], ahi[mt][3],
                     bhi[nt][0], bhi[nt][1]);
                mma8(acc[mt][nt][0], acc[mt][nt][1], acc[mt][nt][2], acc[mt][nt][3],
                     ahi[mt][0], ahi[mt][1], ahi[mt][2], ahi[mt][3],
                     blo[nt][0], blo[nt][1]);
                mma8(acc[mt][nt][0], acc[mt][nt][1], acc[mt][nt][2], acc[mt][nt][3],
                     alo[mt][0], alo[mt][1], alo[mt][2], alo[mt][3],
                     bhi[nt][0], bhi[nt][1]);
            }
        __syncthreads();
        if (t + NSTAGE < NTILES) load_stage(s, t + NSTAGE);
        else CP_COMMIT();   // keep group count aligned
    }
    CP_WAIT0();

    // ---- epilogue: per-warp K-partials -> smem Hp[4][64][33], fixed-order sum ----
    __syncthreads();
    float* Hp = (float*)sm;                       // 4*64*33*4 = 33792 B
#pragma unroll
    for (int mt = 0; mt < 4; mt++) {
        int r0 = mt * 16 + g;
#pragma unroll
        for (int nt = 0; nt < 4; nt++) {
            int cc = nt * 8 + 2 * tq;
            float* Hw = Hp + wid * 64 * 33;
            Hw[r0 * 33 + cc]           = acc[mt][nt][0];
            Hw[r0 * 33 + cc + 1]       = acc[mt][nt][1];
            Hw[(r0 + 8) * 33 + cc]     = acc[mt][nt][2];
            Hw[(r0 + 8) * 33 + cc + 1] = acc[mt][nt][3];
        }
    }
    __syncthreads();

    float h2[32];
    if (tid < MTILE) {
        float h[32];
#pragma unroll
        for (int k = 0; k < 32; k++) {
            // deterministic order: w0 + w1 + w2 + w3
            float v = Hp[tid * 33 + k];
            v += Hp[1 * 64 * 33 + tid * 33 + k];
            v += Hp[2 * 64 * 33 + tid * 33 + k];
            v += Hp[3 * 64 * 33 + tid * 33 + k];
            h[k] = v;
        }
#pragma unroll
        for (int n = 0; n < 32; n++) {
            float s = 0.f;
#pragma unroll
            for (int k = 0; k < 32; k++) s += h[k] * Ws[k * 32 + n];
            h2[n] = s;
        }
        size_t i = m0 + tid;
        if (i < NN) {
            float4* o = (float4*)(g_H2 + i * KO);
#pragma unroll
            for (int n4 = 0; n4 < 8; n4++)
                o[n4] = make_float4(h2[n4*4], h2[n4*4+1], h2[n4*4+2], h2[n4*4+3]);
        } else {
#pragma unroll
            for (int n = 0; n < 32; n++) h2[n] = 0.f;
        }
    }

    // deterministic fixed-order per-CTA BN partial reduction over 64 rows
    __syncthreads();
    float* red = (float*)sm;              // [64][32]
    float* rsq = (float*)(sm + 8192);     // [64][32]
    if (tid < MTILE) {
#pragma unroll
        for (int n = 0; n < 32; n++) {
            red[tid * 32 + n] = h2[n];
            rsq[tid * 32 + n] = h2[n] * h2[n];
        }
    }
    __syncthreads();
    for (int st = 32; st > 0; st >>= 1) {
        if (tid < st) {
#pragma unroll
            for (int n = 0; n < 32; n++) {
                red[tid * 32 + n] += red[(tid + st) * 32 + n];
                rsq[tid * 32 + n] += rsq[(tid + st) * 32 + n];
            }
        }
        __syncthreads();
    }
    if (tid < 32) {
        g_part[blockIdx.x * KO + tid] = red[tid];
        g_psq [blockIdx.x * KO + tid] = rsq[tid];
    }
}

// ================= Kernel 2: finalize BN stats (double) =================
__global__ void k_stats(const float* __restrict__ gamma,
                        const float* __restrict__ beta,
                        const float* __restrict__ bias) {
    int c = threadIdx.x;
    double s = 0.0, qq = 0.0;
    for (int b = 0; b < GRID1; b++) {
        s  += (double)g_part[b * KO + c];
        qq += (double)g_psq [b * KO + c];
    }
    double mean = s / (double)NN;
    double var  = qq / (double)NN - mean * mean;
    double inv  = 1.0 / sqrt(var + 1e-5);
    double gsc  = (double)gamma[c] * inv;
    g_scale[c] = (float)gsc;
    g_shift[c] = (float)((double)beta[c] + (double)bias[c] - mean * gsc);
}

// ================= Kernel 3: out = relu(H2*scale + shift) =================
__global__ void k_apply(float* __restrict__ out) {
    int idx4 = blockIdx.x * blockDim.x + threadIdx.x;
    float4 h  = *(const float4*)(g_H2 + (size_t)idx4 * 4);
    int cb    = (idx4 * 4) & 31;
    float4 sc = *(const float4*)(g_scale + cb);
    float4 sh = *(const float4*)(g_shift + cb);
    float4 o;
    o.x = fmaxf(h.x * sc.x + sh.x, 0.f);
    o.y = fmaxf(h.y * sc.y + sh.y, 0.f);
    o.z = fmaxf(h.z * sc.z + sh.z, 0.f);
    o.w = fmaxf(h.w * sc.w + sh.w, 0.f);
    *(float4*)(out + (size_t)idx4 * 4) = o;
}

// ================= launch =================
extern "C" void kernel_launch(void* const* d_in, const int* in_sizes, int n_in,
                              void* d_out, int out_size) {
    const float* A     = (const float*)d_in[0];
    const float* X     = (const float*)d_in[1];
    const float* W     = (const float*)d_in[2];
    const float* gamma = (const float*)d_in[3];
    const float* beta  = (const float*)d_in[4];
    const float* bias  = (const float*)d_in[5];
    float* out = (float*)d_out;

    cudaFuncSetAttribute(k_gemm1, cudaFuncAttributeMaxDynamicSharedMemorySize, SMEM_TOTAL);

    k_gemm1<<<GRID1, 128, SMEM_TOTAL>>>(A, X, W);
    k_stats<<<1, KO>>>(gamma, beta, bias);
    k_apply<<<(NN * KO / 4) / 256, 256>>>(out);
}